// round 6
// baseline (speedup 1.0000x reference)
#include <cuda_runtime.h>
#include <cuda_bf16.h>
#include <math.h>

#define N_NODES 8192
#define IN_DIM  512
#define H_DIM   128
#define MASK_WPR (N_NODES / 32)   // 256 mask words per row

// Scratch (allocation-free: __device__ globals)
__device__ __nv_bfloat16 g_Whb [(size_t)N_NODES * H_DIM];    // 2 MB bf16
__device__ float         g_s   [N_NODES];
__device__ float         g_inv [N_NODES];
__device__ float         g_wa  [IN_DIM];
__device__ unsigned      g_mask[(size_t)N_NODES * MASK_WPR]; // 8 MB bitmask

// ---------------------------------------------------------------------------
// Kernel 0: wa = W^T @ a
// ---------------------------------------------------------------------------
__global__ __launch_bounds__(256) void k_wa(const float* __restrict__ W,
                                            const float* __restrict__ a) {
    int k = blockIdx.x * 256 + threadIdx.x;
    float sum = 0.f;
#pragma unroll 4
    for (int hd = 0; hd < H_DIM; hd++)
        sum += a[hd] * W[(size_t)hd * IN_DIM + k];
    g_wa[k] = sum;
}

// ---------------------------------------------------------------------------
// Kernel 1: s[i] = h[i,:] . wa   (warp per row)
// ---------------------------------------------------------------------------
__global__ __launch_bounds__(256) void k_s(const float* __restrict__ h) {
    int row  = (blockIdx.x * blockDim.x + threadIdx.x) >> 5;
    int lane = threadIdx.x & 31;
    const float4* h4  = (const float4*)(h + (size_t)row * IN_DIM);
    const float4* wa4 = (const float4*)g_wa;
    float d = 0.f;
#pragma unroll
    for (int u = 0; u < 4; u++) {
        float4 x = h4[lane + 32 * u];
        float4 y = __ldg(&wa4[lane + 32 * u]);
        d += x.x * y.x + x.y * y.y + x.z * y.z + x.w * y.w;
    }
#pragma unroll
    for (int o = 16; o; o >>= 1) d += __shfl_xor_sync(0xffffffffu, d, o);
    if (lane == 0) g_s[row] = d;
}

// ---------------------------------------------------------------------------
// Kernel 2 (horizontally fused): blocks 0..127 = Whb gemm (BM=64),
// blocks 128..8319 = per-row denom + bitmask. Overlaps FMA- and DRAM-bound work.
// ---------------------------------------------------------------------------
#define GEMM_BLOCKS (N_NODES / 64)

__global__ __launch_bounds__(256) void k_gd(const float* __restrict__ h,
                                            const float* __restrict__ W,
                                            const float* __restrict__ b,
                                            const float* __restrict__ adj) {
    __shared__ float hs[64][33];
    __shared__ float ws[128][33];
    __shared__ float red[8];

    const int t = threadIdx.x;

    if (blockIdx.x < GEMM_BLOCKS) {
        // ================= GEMM path =================
        const int m0 = blockIdx.x * 64;
        const int tm = t >> 4;
        const int tn = t & 15;
        float acc[4][8];
#pragma unroll
        for (int v = 0; v < 4; v++)
#pragma unroll
            for (int u = 0; u < 8; u++) acc[v][u] = 0.f;

        for (int k0 = 0; k0 < IN_DIM; k0 += 32) {
#pragma unroll
            for (int p = 0; p < 8; p++) {
                int idx = t + p * 256;
                int r = idx >> 5, c = idx & 31;
                hs[r][c] = h[(size_t)(m0 + r) * IN_DIM + k0 + c];
            }
#pragma unroll
            for (int p = 0; p < 16; p++) {
                int idx = t + p * 256;
                int r = idx >> 5, c = idx & 31;
                ws[r][c] = W[(size_t)r * IN_DIM + k0 + c];
            }
            __syncthreads();
#pragma unroll
            for (int k = 0; k < 32; k++) {
                float av[4], bv[8];
#pragma unroll
                for (int v = 0; v < 4; v++) av[v] = hs[tm * 4 + v][k];
#pragma unroll
                for (int u = 0; u < 8; u++) bv[u] = ws[tn + 16 * u][k];
#pragma unroll
                for (int v = 0; v < 4; v++)
#pragma unroll
                    for (int u = 0; u < 8; u++)
                        acc[v][u] += av[v] * bv[u];
            }
            __syncthreads();
        }
#pragma unroll
        for (int v = 0; v < 4; v++) {
            int i = m0 + tm * 4 + v;
#pragma unroll
            for (int u = 0; u < 8; u++) {
                int hd = tn + 16 * u;
                g_Whb[(size_t)i * H_DIM + hd] =
                    __float2bfloat16(acc[v][u] + b[hd]);
            }
        }
    } else {
        // ================= DENOM + MASK path =================
        const int i    = blockIdx.x - GEMM_BLOCKS;
        const int lane = t & 31;
        const int wid  = t >> 5;

        const float si = __ldg(&g_s[i]);
        const float4* __restrict__ row4 = (const float4*)(adj + (size_t)i * N_NODES);
        const float4* __restrict__ s4   = (const float4*)g_s;
        uint4* __restrict__ mrow = (uint4*)(g_mask + (size_t)i * MASK_WPR);

        float dsum = 0.f;
#pragma unroll
        for (int step = 0; step < 8; step++) {
            int grp = wid * 8 + step;
            int c4  = grp * 32 + lane;
            float4 a4 = __ldcs(&row4[c4]);
            float4 sj = __ldg(&s4[c4]);
            unsigned nib = (a4.x != 0.f) | ((a4.y != 0.f) << 1)
                         | ((a4.z != 0.f) << 2) | ((a4.w != 0.f) << 3);
            unsigned b0 = __ballot_sync(0xffffffffu, nib & 1u);
            unsigned b1 = __ballot_sync(0xffffffffu, nib & 2u);
            unsigned b2 = __ballot_sync(0xffffffffu, nib & 4u);
            unsigned b3 = __ballot_sync(0xffffffffu, nib & 8u);
            if (lane == 0) mrow[grp] = make_uint4(b0, b1, b2, b3);

            float x0 = si + sj.x, x1 = si + sj.y;
            float x2 = si + sj.z, x3 = si + sj.w;
            x0 = x0 > 0.f ? x0 : 0.2f * x0;
            x1 = x1 > 0.f ? x1 : 0.2f * x1;
            x2 = x2 > 0.f ? x2 : 0.2f * x2;
            x3 = x3 > 0.f ? x3 : 0.2f * x3;
            if (a4.x != 0.f) dsum += __expf(x0);
            if (a4.y != 0.f) dsum += __expf(x1);
            if (a4.z != 0.f) dsum += __expf(x2);
            if (a4.w != 0.f) dsum += __expf(x3);
        }
#pragma unroll
        for (int o = 16; o; o >>= 1)
            dsum += __shfl_xor_sync(0xffffffffu, dsum, o);
        if (lane == 0) red[wid] = dsum;
        __syncthreads();
        if (t == 0) {
            float tot = 0.f;
#pragma unroll
            for (int w = 0; w < 8; w++) tot += red[w];
            g_inv[i] = (tot > 0.f) ? 1.f / tot : 0.f;
        }
    }
}

// ---------------------------------------------------------------------------
// Kernel 3 (fused, single-sync pipeline): RT=64 rows/CTA, 512 threads.
// Per chunk c: issue cp.async Bs(c+1), compute alpha(c+1) -> As[other]+gmem,
// MMA on As[buf] x Bs[buf], wait, ONE syncthreads.
// ---------------------------------------------------------------------------
#define RT 64
#define CT 128
#define NTHREADS 512
#define NCHUNK (N_NODES / CT)
#define APAD 136
#define ROWB (APAD * 2)
#define AS_BYTES (RT * APAD * 2)           // 17408
#define BS_BYTES (CT * APAD * 2)           // 34816
#define OFF_BS   (2 * AS_BYTES)
#define OFF_SL   (OFF_BS + 2 * BS_BYTES)
#define SMEM_TOTAL (OFF_SL + 2 * RT * 4)   // 104,960 B

__device__ __forceinline__ void mma16816(float* c, const unsigned* a,
                                         unsigned b0, unsigned b1) {
    asm volatile(
        "mma.sync.aligned.m16n8k16.row.col.f32.bf16.bf16.f32 "
        "{%0,%1,%2,%3}, {%4,%5,%6,%7}, {%8,%9}, {%0,%1,%2,%3};"
        : "+f"(c[0]), "+f"(c[1]), "+f"(c[2]), "+f"(c[3])
        : "r"(a[0]), "r"(a[1]), "r"(a[2]), "r"(a[3]), "r"(b0), "r"(b1));
}

__device__ __forceinline__ void cp16(unsigned dst, const void* src) {
    asm volatile("cp.async.cg.shared.global [%0], [%1], 16;\n"
                 :: "r"(dst), "l"(src));
}

__global__ __launch_bounds__(NTHREADS) void k_fused(float* __restrict__ z_out,
                                                    float* __restrict__ alpha_out) {
    extern __shared__ char smem[];
    __nv_bfloat16* As   = (__nv_bfloat16*)smem;          // 2 buffers
    float*         sloc = (float*)(smem + OFF_SL);
    float*         invl = sloc + RT;

    const int t    = threadIdx.x;
    const int lane = t & 31;
    const int wid  = t >> 5;            // 0..15
    const int i0   = blockIdx.x * RT;

    const unsigned as_base = (unsigned)__cvta_generic_to_shared(As);
    const unsigned bs_base = (unsigned)__cvta_generic_to_shared(smem + OFF_BS);

    if (t < RT) {
        sloc[t] = g_s[i0 + t];
        invl[t] = g_inv[i0 + t];
    }

    // prologue: Bs chunk 0
#pragma unroll
    for (int p = 0; p < 4; p++) {
        int idx = t + p * NTHREADS;
        int jr = idx >> 4, u = idx & 15;
        cp16(bs_base + jr * ROWB + u * 16, (const char*)g_Whb + idx * 16);
    }
    asm volatile("cp.async.commit_group;");
    __syncthreads();   // sloc/invl ready

    const float4* s4g = (const float4*)g_s;
    const uint4*  m4g = (const uint4*)g_mask;

    // ---- alpha chunk 0 -> As[0] ----
    {
        float4 sj = __ldg(&s4g[lane]);
#pragma unroll
        for (int p = 0; p < 4; p++) {
            int r = wid * 4 + p;
            uint4 mw = __ldg(&m4g[(size_t)(i0 + r) * (MASK_WPR / 4)]);
            float si = sloc[r], inv = invl[r];
            float4 ex;
            { float x = si + sj.x; x = x > 0.f ? x : 0.2f * x;
              ex.x = ((mw.x >> lane) & 1u) ? __expf(x) * inv : 0.f; }
            { float x = si + sj.y; x = x > 0.f ? x : 0.2f * x;
              ex.y = ((mw.y >> lane) & 1u) ? __expf(x) * inv : 0.f; }
            { float x = si + sj.z; x = x > 0.f ? x : 0.2f * x;
              ex.z = ((mw.z >> lane) & 1u) ? __expf(x) * inv : 0.f; }
            { float x = si + sj.w; x = x > 0.f ? x : 0.2f * x;
              ex.w = ((mw.w >> lane) & 1u) ? __expf(x) * inv : 0.f; }
            __stcs((float4*)(alpha_out + (size_t)(i0 + r) * N_NODES) + lane, ex);
            __nv_bfloat162* dst = (__nv_bfloat162*)&As[r * APAD + lane * 4];
            dst[0] = __float22bfloat162_rn(make_float2(ex.x, ex.y));
            dst[1] = __float22bfloat162_rn(make_float2(ex.z, ex.w));
        }
    }
    asm volatile("cp.async.wait_group 0;");
    __syncthreads();

    const int wm = wid >> 2;     // 0..3
    const int wn = wid & 3;      // 0..3
    float acc[4][4];
#pragma unroll
    for (int n = 0; n < 4; n++)
#pragma unroll
        for (int c = 0; c < 4; c++) acc[n][c] = 0.f;

    const unsigned a_off0 = (wm * 16 + (lane & 15)) * ROWB + ((lane >> 4) * 8) * 2;
    const unsigned b_rowsel = (lane & 15);
    const unsigned b_colsel = (lane >> 4) * 8;

    for (int c = 0; c < NCHUNK; c++) {
        const int buf = c & 1;

        if (c + 1 < NCHUNK) {
            // cp.async: Bs chunk c+1 -> Bs[buf^1]
            const char* src = (const char*)(g_Whb + (size_t)(c + 1) * CT * H_DIM);
            const unsigned bdst = bs_base + (buf ^ 1) * BS_BYTES;
#pragma unroll
            for (int p = 0; p < 4; p++) {
                int idx = t + p * NTHREADS;
                int jr = idx >> 4, u = idx & 15;
                cp16(bdst + jr * ROWB + u * 16, src + idx * 16);
            }
            asm volatile("cp.async.commit_group;");

            // alpha chunk c+1 -> As[buf^1] + gmem
            __nv_bfloat16* Ad = As + (buf ^ 1) * (AS_BYTES / 2);
            float4 sj = __ldg(&s4g[(c + 1) * 32 + lane]);
#pragma unroll
            for (int p = 0; p < 4; p++) {
                int r = wid * 4 + p;
                uint4 mw = __ldg(&m4g[(size_t)(i0 + r) * (MASK_WPR / 4) + c + 1]);
                float si = sloc[r], inv = invl[r];
                float4 ex;
                { float x = si + sj.x; x = x > 0.f ? x : 0.2f * x;
                  ex.x = ((mw.x >> lane) & 1u) ? __expf(x) * inv : 0.f; }
                { float x = si + sj.y; x = x > 0.f ? x : 0.2f * x;
                  ex.y = ((mw.y >> lane) & 1u) ? __expf(x) * inv : 0.f; }
                { float x = si + sj.z; x = x > 0.f ? x : 0.2f * x;
                  ex.z = ((mw.z >> lane) & 1u) ? __expf(x) * inv : 0.f; }
                { float x = si + sj.w; x = x > 0.f ? x : 0.2f * x;
                  ex.w = ((mw.w >> lane) & 1u) ? __expf(x) * inv : 0.f; }
                __stcs((float4*)(alpha_out + (size_t)(i0 + r) * N_NODES
                                 + (c + 1) * CT) + lane, ex);
                __nv_bfloat162* dst = (__nv_bfloat162*)&Ad[r * APAD + lane * 4];
                dst[0] = __float22bfloat162_rn(make_float2(ex.x, ex.y));
                dst[1] = __float22bfloat162_rn(make_float2(ex.z, ex.w));
            }
        }

        // ---- MMA on As[buf] x Bs[buf] ----
        const unsigned abuf = as_base + buf * AS_BYTES + a_off0;
        const unsigned bbuf = bs_base + buf * BS_BYTES;
#pragma unroll
        for (int kk = 0; kk < CT; kk += 16) {
            unsigned a[4];
            asm volatile(
                "ldmatrix.sync.aligned.m8n8.x4.shared.b16 {%0,%1,%2,%3}, [%4];"
                : "=r"(a[0]), "=r"(a[1]), "=r"(a[2]), "=r"(a[3])
                : "r"(abuf + kk * 2));
#pragma unroll
            for (int half = 0; half < 2; half++) {
                int n0 = wn * 32 + half * 16;
                unsigned baddr = bbuf + (kk + b_rowsel) * ROWB
                                      + (n0 + b_colsel) * 2;
                unsigned b[4];
                asm volatile(
                    "ldmatrix.sync.aligned.m8n8.x4.trans.shared.b16 "
                    "{%0,%1,%2,%3}, [%4];"
                    : "=r"(b[0]), "=r"(b[1]), "=r"(b[2]), "=r"(b[3])
                    : "r"(baddr));
                mma16816(acc[half * 2 + 0], a, b[0], b[1]);
                mma16816(acc[half * 2 + 1], a, b[2], b[3]);
            }
        }

        if (c + 1 < NCHUNK)
            asm volatile("cp.async.wait_group 0;");
        __syncthreads();
    }

    // ---- epilogue: z = sigmoid(acc) ----
    const int g = lane >> 2, q = lane & 3;
    const size_t r0 = (size_t)(i0 + wm * 16 + g) * H_DIM;
    const size_t r1 = r0 + 8 * H_DIM;
#pragma unroll
    for (int nt = 0; nt < 4; nt++) {
        int col = wn * 32 + nt * 8 + 2 * q;
        z_out[r0 + col]     = 1.f / (1.f + __expf(-acc[nt][0]));
        z_out[r0 + col + 1] = 1.f / (1.f + __expf(-acc[nt][1]));
        z_out[r1 + col]     = 1.f / (1.f + __expf(-acc[nt][2]));
        z_out[r1 + col + 1] = 1.f / (1.f + __expf(-acc[nt][3]));
    }
}

// ---------------------------------------------------------------------------
extern "C" void kernel_launch(void* const* d_in, const int* in_sizes, int n_in,
                              void* d_out, int out_size) {
    const float* h   = (const float*)d_in[0];  // (8192, 512)
    const float* adj = (const float*)d_in[1];  // (8192, 8192)
    const float* W   = (const float*)d_in[2];  // (128, 512)
    const float* b   = (const float*)d_in[3];  // (128,)
    const float* a   = (const float*)d_in[4];  // (1, 128)

    float* z_out     = (float*)d_out;
    float* alpha_out = z_out + (size_t)N_NODES * H_DIM;

    k_wa<<<IN_DIM / 256, 256>>>(W, a);
    k_s<<<N_NODES / 8, 256>>>(h);
    k_gd<<<GEMM_BLOCKS + N_NODES, 256>>>(h, W, b, adj);

    cudaFuncSetAttribute(k_fused, cudaFuncAttributeMaxDynamicSharedMemorySize,
                         SMEM_TOTAL);
    k_fused<<<N_NODES / RT, NTHREADS, SMEM_TOTAL>>>(z_out, alpha_out);
}

// round 7
// speedup vs baseline: 1.3499x; 1.3499x over previous
#include <cuda_runtime.h>
#include <cuda_bf16.h>
#include <math.h>

#define N_NODES 8192
#define IN_DIM  512
#define H_DIM   128
#define MASK_WPR (N_NODES / 32)   // 256 mask words per row

// Scratch (allocation-free: __device__ globals)
__device__ __nv_bfloat16 g_Whb [(size_t)N_NODES * H_DIM];    // 2 MB bf16
__device__ float         g_s   [N_NODES];
__device__ float         g_inv [N_NODES];
__device__ float         g_wa  [IN_DIM];
__device__ unsigned      g_mask[(size_t)N_NODES * MASK_WPR]; // 8 MB bitmask
__device__ float         g_part[2 * (size_t)N_NODES * H_DIM]; // 8 MB partials

// ---------------------------------------------------------------------------
// Kernel 0: wa = W^T @ a
// ---------------------------------------------------------------------------
__global__ __launch_bounds__(256) void k_wa(const float* __restrict__ W,
                                            const float* __restrict__ a) {
    int k = blockIdx.x * 256 + threadIdx.x;
    float sum = 0.f;
#pragma unroll 4
    for (int hd = 0; hd < H_DIM; hd++)
        sum += a[hd] * W[(size_t)hd * IN_DIM + k];
    g_wa[k] = sum;
}

// ---------------------------------------------------------------------------
// Kernel 1: s[i] = h[i,:] . wa   (warp per row)
// ---------------------------------------------------------------------------
__global__ __launch_bounds__(256) void k_s(const float* __restrict__ h) {
    int row  = (blockIdx.x * blockDim.x + threadIdx.x) >> 5;
    int lane = threadIdx.x & 31;
    const float4* h4  = (const float4*)(h + (size_t)row * IN_DIM);
    const float4* wa4 = (const float4*)g_wa;
    float d = 0.f;
#pragma unroll
    for (int u = 0; u < 4; u++) {
        float4 x = h4[lane + 32 * u];
        float4 y = __ldg(&wa4[lane + 32 * u]);
        d += x.x * y.x + x.y * y.y + x.z * y.z + x.w * y.w;
    }
#pragma unroll
    for (int o = 16; o; o >>= 1) d += __shfl_xor_sync(0xffffffffu, d, o);
    if (lane == 0) g_s[row] = d;
}

// ---------------------------------------------------------------------------
// Kernel 2: Whb = bf16(h @ W^T + b)  (proven BM=64 fp32 gemm, 47.5us)
// ---------------------------------------------------------------------------
__global__ __launch_bounds__(256) void k_gemm_wh(const float* __restrict__ h,
                                                 const float* __restrict__ W,
                                                 const float* __restrict__ b) {
    __shared__ float hs[64][33];
    __shared__ float ws[128][33];
    const int m0 = blockIdx.x * 64;
    const int t  = threadIdx.x;
    const int tm = t >> 4;
    const int tn = t & 15;
    float acc[4][8];
#pragma unroll
    for (int v = 0; v < 4; v++)
#pragma unroll
        for (int u = 0; u < 8; u++) acc[v][u] = 0.f;

    for (int k0 = 0; k0 < IN_DIM; k0 += 32) {
#pragma unroll
        for (int p = 0; p < 8; p++) {
            int idx = t + p * 256;
            int r = idx >> 5, c = idx & 31;
            hs[r][c] = h[(size_t)(m0 + r) * IN_DIM + k0 + c];
        }
#pragma unroll
        for (int p = 0; p < 16; p++) {
            int idx = t + p * 256;
            int r = idx >> 5, c = idx & 31;
            ws[r][c] = W[(size_t)r * IN_DIM + k0 + c];
        }
        __syncthreads();
#pragma unroll
        for (int k = 0; k < 32; k++) {
            float av[4], bv[8];
#pragma unroll
            for (int v = 0; v < 4; v++) av[v] = hs[tm * 4 + v][k];
#pragma unroll
            for (int u = 0; u < 8; u++) bv[u] = ws[tn + 16 * u][k];
#pragma unroll
            for (int v = 0; v < 4; v++)
#pragma unroll
                for (int u = 0; u < 8; u++)
                    acc[v][u] += av[v] * bv[u];
        }
        __syncthreads();
    }
#pragma unroll
    for (int v = 0; v < 4; v++) {
        int i = m0 + tm * 4 + v;
#pragma unroll
        for (int u = 0; u < 8; u++) {
            int hd = tn + 16 * u;
            g_Whb[(size_t)i * H_DIM + hd] = __float2bfloat16(acc[v][u] + b[hd]);
        }
    }
}

// ---------------------------------------------------------------------------
// Kernel 3: per-row denom + bitmask (adj read exactly once per row)
// ---------------------------------------------------------------------------
__global__ __launch_bounds__(256) void k_denom(const float* __restrict__ adj) {
    const int i    = blockIdx.x;
    const int t    = threadIdx.x;
    const int lane = t & 31;
    const int wid  = t >> 5;

    const float si = __ldg(&g_s[i]);
    const float4* __restrict__ row4 = (const float4*)(adj + (size_t)i * N_NODES);
    const float4* __restrict__ s4   = (const float4*)g_s;
    uint4* __restrict__ mrow = (uint4*)(g_mask + (size_t)i * MASK_WPR);

    float dsum = 0.f;
#pragma unroll
    for (int step = 0; step < 8; step++) {
        int grp = wid * 8 + step;
        int c4  = grp * 32 + lane;
        float4 a4 = __ldcs(&row4[c4]);
        float4 sj = __ldg(&s4[c4]);
        unsigned nib = (a4.x != 0.f) | ((a4.y != 0.f) << 1)
                     | ((a4.z != 0.f) << 2) | ((a4.w != 0.f) << 3);
        unsigned b0 = __ballot_sync(0xffffffffu, nib & 1u);
        unsigned b1 = __ballot_sync(0xffffffffu, nib & 2u);
        unsigned b2 = __ballot_sync(0xffffffffu, nib & 4u);
        unsigned b3 = __ballot_sync(0xffffffffu, nib & 8u);
        if (lane == 0) mrow[grp] = make_uint4(b0, b1, b2, b3);

        float x0 = si + sj.x, x1 = si + sj.y;
        float x2 = si + sj.z, x3 = si + sj.w;
        x0 = x0 > 0.f ? x0 : 0.2f * x0;
        x1 = x1 > 0.f ? x1 : 0.2f * x1;
        x2 = x2 > 0.f ? x2 : 0.2f * x2;
        x3 = x3 > 0.f ? x3 : 0.2f * x3;
        if (a4.x != 0.f) dsum += __expf(x0);
        if (a4.y != 0.f) dsum += __expf(x1);
        if (a4.z != 0.f) dsum += __expf(x2);
        if (a4.w != 0.f) dsum += __expf(x3);
    }
#pragma unroll
    for (int o = 16; o; o >>= 1) dsum += __shfl_xor_sync(0xffffffffu, dsum, o);
    __shared__ float red[8];
    if (lane == 0) red[wid] = dsum;
    __syncthreads();
    if (t == 0) {
        float tot = 0.f;
#pragma unroll
        for (int w = 0; w < 8; w++) tot += red[w];
        g_inv[i] = (tot > 0.f) ? 1.f / tot : 0.f;
    }
}

// ---------------------------------------------------------------------------
// Kernel 4 (fused): RT=64 rows, JSPLIT=2 over j, 256 thr, grid=256 (2 CTAs/SM).
// Single-sync pipeline, double-buffered As+Bs. Writes fp32 partial acc.
// ---------------------------------------------------------------------------
#define RT 64
#define CT 128
#define NTH 256
#define JSPLIT 2
#define CHUNKS (N_NODES / CT / JSPLIT)     // 32 per CTA
#define APAD 136
#define ROWB (APAD * 2)
#define AS_BYTES (RT * APAD * 2)           // 17408
#define BS_BYTES (CT * APAD * 2)           // 34816
#define OFF_BS   (2 * AS_BYTES)
#define OFF_SL   (OFF_BS + 2 * BS_BYTES)
#define SMEM_TOTAL (OFF_SL + 2 * RT * 4)   // 104,960 B

__device__ __forceinline__ void mma16816(float* c, const unsigned* a,
                                         unsigned b0, unsigned b1) {
    asm volatile(
        "mma.sync.aligned.m16n8k16.row.col.f32.bf16.bf16.f32 "
        "{%0,%1,%2,%3}, {%4,%5,%6,%7}, {%8,%9}, {%0,%1,%2,%3};"
        : "+f"(c[0]), "+f"(c[1]), "+f"(c[2]), "+f"(c[3])
        : "r"(a[0]), "r"(a[1]), "r"(a[2]), "r"(a[3]), "r"(b0), "r"(b1));
}

__device__ __forceinline__ void cp16(unsigned dst, const void* src) {
    asm volatile("cp.async.cg.shared.global [%0], [%1], 16;\n"
                 :: "r"(dst), "l"(src));
}

__device__ __forceinline__ void alpha_tile(
    __nv_bfloat16* Ad, float* __restrict__ alpha_out,
    const uint4* m4g, const float4* s4g, const float* sloc, const float* invl,
    int i0, int jc, int wid, int lane)
{
    float4 sj = __ldg(&s4g[jc * 32 + lane]);
#pragma unroll
    for (int p = 0; p < 8; p++) {
        int r = wid * 8 + p;
        uint4 mw = __ldg(&m4g[(size_t)(i0 + r) * (MASK_WPR / 4) + jc]);
        float si = sloc[r], inv = invl[r];
        float4 ex;
        { float x = si + sj.x; x = x > 0.f ? x : 0.2f * x;
          ex.x = ((mw.x >> lane) & 1u) ? __expf(x) * inv : 0.f; }
        { float x = si + sj.y; x = x > 0.f ? x : 0.2f * x;
          ex.y = ((mw.y >> lane) & 1u) ? __expf(x) * inv : 0.f; }
        { float x = si + sj.z; x = x > 0.f ? x : 0.2f * x;
          ex.z = ((mw.z >> lane) & 1u) ? __expf(x) * inv : 0.f; }
        { float x = si + sj.w; x = x > 0.f ? x : 0.2f * x;
          ex.w = ((mw.w >> lane) & 1u) ? __expf(x) * inv : 0.f; }
        __stcs((float4*)(alpha_out + (size_t)(i0 + r) * N_NODES
                         + (size_t)jc * CT) + lane, ex);
        __nv_bfloat162* dst = (__nv_bfloat162*)&Ad[r * APAD + lane * 4];
        dst[0] = __float22bfloat162_rn(make_float2(ex.x, ex.y));
        dst[1] = __float22bfloat162_rn(make_float2(ex.z, ex.w));
    }
}

__global__ __launch_bounds__(NTH, 2) void k_fused(float* __restrict__ alpha_out) {
    extern __shared__ char smem[];
    __nv_bfloat16* As   = (__nv_bfloat16*)smem;            // 2 buffers
    float*         sloc = (float*)(smem + OFF_SL);
    float*         invl = sloc + RT;

    const int t    = threadIdx.x;
    const int lane = t & 31;
    const int wid  = t >> 5;                 // 0..7
    const int ib   = blockIdx.x & 127;
    const int js   = blockIdx.x >> 7;
    const int i0   = ib * RT;
    const int c0   = js * CHUNKS;

    const unsigned as_base = (unsigned)__cvta_generic_to_shared(As);
    const unsigned bs_base = (unsigned)__cvta_generic_to_shared(smem + OFF_BS);

    if (t < RT) {
        sloc[t] = g_s[i0 + t];
        invl[t] = g_inv[i0 + t];
    }

    // prologue: Bs chunk c0
    {
        const char* src = (const char*)(g_Whb + (size_t)c0 * CT * H_DIM);
#pragma unroll
        for (int p = 0; p < 8; p++) {
            int idx = t + p * NTH;
            int jr = idx >> 4, u = idx & 15;
            cp16(bs_base + jr * ROWB + u * 16, src + idx * 16);
        }
        asm volatile("cp.async.commit_group;");
    }
    __syncthreads();   // sloc/invl ready

    const float4* s4g = (const float4*)g_s;
    const uint4*  m4g = (const uint4*)g_mask;

    // alpha chunk c0 -> As[0]
    alpha_tile(As, alpha_out, m4g, s4g, sloc, invl, i0, c0, wid, lane);
    asm volatile("cp.async.wait_group 0;");
    __syncthreads();

    const int wm = wid >> 1;     // 0..3 -> rows wm*16
    const int wn = wid & 1;      // 0..1 -> cols wn*64
    float acc[8][4];
#pragma unroll
    for (int n = 0; n < 8; n++)
#pragma unroll
        for (int c = 0; c < 4; c++) acc[n][c] = 0.f;

    const unsigned a_off0 = (wm * 16 + (lane & 15)) * ROWB + ((lane >> 4) * 8) * 2;
    const unsigned b_rowsel = (lane & 15);
    const unsigned b_colsel = (lane >> 4) * 8;

    for (int cc = 0; cc < CHUNKS; cc++) {
        const int buf = cc & 1;
        const int jc  = c0 + cc;

        if (cc + 1 < CHUNKS) {
            // cp.async next Bs
            const char* src = (const char*)(g_Whb + (size_t)(jc + 1) * CT * H_DIM);
            const unsigned bdst = bs_base + (buf ^ 1) * BS_BYTES;
#pragma unroll
            for (int p = 0; p < 8; p++) {
                int idx = t + p * NTH;
                int jr = idx >> 4, u = idx & 15;
                cp16(bdst + jr * ROWB + u * 16, src + idx * 16);
            }
            asm volatile("cp.async.commit_group;");
            // alpha next chunk -> As[buf^1]
            alpha_tile(As + (buf ^ 1) * (RT * APAD), alpha_out,
                       m4g, s4g, sloc, invl, i0, jc + 1, wid, lane);
        }

        // MMA As[buf] x Bs[buf]
        const unsigned abuf = as_base + buf * AS_BYTES + a_off0;
        const unsigned bbuf = bs_base + buf * BS_BYTES;
#pragma unroll
        for (int kk = 0; kk < CT; kk += 16) {
            unsigned a[4];
            asm volatile(
                "ldmatrix.sync.aligned.m8n8.x4.shared.b16 {%0,%1,%2,%3}, [%4];"
                : "=r"(a[0]), "=r"(a[1]), "=r"(a[2]), "=r"(a[3])
                : "r"(abuf + kk * 2));
#pragma unroll
            for (int nt = 0; nt < 4; nt++) {
                int n0 = wn * 64 + nt * 16;
                unsigned baddr = bbuf + (kk + b_rowsel) * ROWB
                                      + (n0 + b_colsel) * 2;
                unsigned b[4];
                asm volatile(
                    "ldmatrix.sync.aligned.m8n8.x4.trans.shared.b16 "
                    "{%0,%1,%2,%3}, [%4];"
                    : "=r"(b[0]), "=r"(b[1]), "=r"(b[2]), "=r"(b[3])
                    : "r"(baddr));
                mma16816(acc[nt * 2 + 0], a, b[0], b[1]);
                mma16816(acc[nt * 2 + 1], a, b[2], b[3]);
            }
        }

        if (cc + 1 < CHUNKS)
            asm volatile("cp.async.wait_group 0;");
        __syncthreads();
    }

    // epilogue: write fp32 partials
    float* part = g_part + (size_t)js * N_NODES * H_DIM;
    const int g = lane >> 2, q = lane & 3;
    const size_t r0 = (size_t)(i0 + wm * 16 + g) * H_DIM;
    const size_t r1 = r0 + 8 * H_DIM;
#pragma unroll
    for (int m = 0; m < 8; m++) {
        int col = wn * 64 + m * 8 + 2 * q;
        part[r0 + col]     = acc[m][0];
        part[r0 + col + 1] = acc[m][1];
        part[r1 + col]     = acc[m][2];
        part[r1 + col + 1] = acc[m][3];
    }
}

// ---------------------------------------------------------------------------
// Kernel 5: z = sigmoid(part0 + part1)
// ---------------------------------------------------------------------------
__global__ __launch_bounds__(256) void k_z(float* __restrict__ z_out) {
    int idx = blockIdx.x * 256 + threadIdx.x;      // float4 index
    const float4* p0 = (const float4*)g_part;
    const float4* p1 = (const float4*)(g_part + (size_t)N_NODES * H_DIM);
    float4 u = p0[idx], v = p1[idx];
    float4 z;
    z.x = 1.f / (1.f + __expf(-(u.x + v.x)));
    z.y = 1.f / (1.f + __expf(-(u.y + v.y)));
    z.z = 1.f / (1.f + __expf(-(u.z + v.z)));
    z.w = 1.f / (1.f + __expf(-(u.w + v.w)));
    ((float4*)z_out)[idx] = z;
}

// ---------------------------------------------------------------------------
extern "C" void kernel_launch(void* const* d_in, const int* in_sizes, int n_in,
                              void* d_out, int out_size) {
    const float* h   = (const float*)d_in[0];  // (8192, 512)
    const float* adj = (const float*)d_in[1];  // (8192, 8192)
    const float* W   = (const float*)d_in[2];  // (128, 512)
    const float* b   = (const float*)d_in[3];  // (128,)
    const float* a   = (const float*)d_in[4];  // (1, 128)

    float* z_out     = (float*)d_out;
    float* alpha_out = z_out + (size_t)N_NODES * H_DIM;

    k_wa<<<IN_DIM / 256, 256>>>(W, a);
    k_s<<<N_NODES / 8, 256>>>(h);
    k_gemm_wh<<<N_NODES / 64, 256>>>(h, W, b);
    k_denom<<<N_NODES, 256>>>(adj);

    cudaFuncSetAttribute(k_fused, cudaFuncAttributeMaxDynamicSharedMemorySize,
                         SMEM_TOTAL);
    k_fused<<<128 * JSPLIT, NTH, SMEM_TOTAL>>>(alpha_out);

    k_z<<<(N_NODES * H_DIM / 4) / 256, 256>>>(z_out);
}

// round 8
// speedup vs baseline: 1.5060x; 1.1156x over previous
#include <cuda_runtime.h>
#include <cuda_bf16.h>
#include <math.h>

#define N_NODES 8192
#define IN_DIM  512
#define H_DIM   128
#define MASK_WPR (N_NODES / 32)   // 256 mask words per row

// Scratch (allocation-free: __device__ globals)
__device__ __nv_bfloat16 g_Whb [(size_t)N_NODES * H_DIM];    // 2 MB bf16
__device__ float         g_s   [N_NODES];
__device__ float         g_E   [N_NODES];   // exp(s)
__device__ float         g_E2  [N_NODES];   // exp(0.2 s)
__device__ float         g_inv [N_NODES];
__device__ float         g_wa  [IN_DIM];
__device__ unsigned      g_mask[(size_t)N_NODES * MASK_WPR]; // 8 MB bitmask
__device__ float         g_part[2 * (size_t)N_NODES * H_DIM]; // 8 MB partials

// ---------------------------------------------------------------------------
// Kernel 0: wa = W^T @ a
// ---------------------------------------------------------------------------
__global__ __launch_bounds__(256) void k_wa(const float* __restrict__ W,
                                            const float* __restrict__ a) {
    int k = blockIdx.x * 256 + threadIdx.x;
    float sum = 0.f;
#pragma unroll 4
    for (int hd = 0; hd < H_DIM; hd++)
        sum += a[hd] * W[(size_t)hd * IN_DIM + k];
    g_wa[k] = sum;
}

// ---------------------------------------------------------------------------
// Kernel 1: s[i] = h[i,:] . wa ; E = exp(s); E2 = exp(0.2 s)
// ---------------------------------------------------------------------------
__global__ __launch_bounds__(256) void k_s(const float* __restrict__ h) {
    int row  = (blockIdx.x * blockDim.x + threadIdx.x) >> 5;
    int lane = threadIdx.x & 31;
    const float4* h4  = (const float4*)(h + (size_t)row * IN_DIM);
    const float4* wa4 = (const float4*)g_wa;
    float d = 0.f;
#pragma unroll
    for (int u = 0; u < 4; u++) {
        float4 x = h4[lane + 32 * u];
        float4 y = __ldg(&wa4[lane + 32 * u]);
        d += x.x * y.x + x.y * y.y + x.z * y.z + x.w * y.w;
    }
#pragma unroll
    for (int o = 16; o; o >>= 1) d += __shfl_xor_sync(0xffffffffu, d, o);
    if (lane == 0) {
        g_s [row] = d;
        g_E [row] = __expf(d);
        g_E2[row] = __expf(0.2f * d);
    }
}

// ---------------------------------------------------------------------------
// Kernel 2: Whb = bf16(h @ W^T + b)  (proven BM=64 fp32 gemm)
// ---------------------------------------------------------------------------
__global__ __launch_bounds__(256) void k_gemm_wh(const float* __restrict__ h,
                                                 const float* __restrict__ W,
                                                 const float* __restrict__ b) {
    __shared__ float hs[64][33];
    __shared__ float ws[128][33];
    const int m0 = blockIdx.x * 64;
    const int t  = threadIdx.x;
    const int tm = t >> 4;
    const int tn = t & 15;
    float acc[4][8];
#pragma unroll
    for (int v = 0; v < 4; v++)
#pragma unroll
        for (int u = 0; u < 8; u++) acc[v][u] = 0.f;

    for (int k0 = 0; k0 < IN_DIM; k0 += 32) {
#pragma unroll
        for (int p = 0; p < 8; p++) {
            int idx = t + p * 256;
            int r = idx >> 5, c = idx & 31;
            hs[r][c] = h[(size_t)(m0 + r) * IN_DIM + k0 + c];
        }
#pragma unroll
        for (int p = 0; p < 16; p++) {
            int idx = t + p * 256;
            int r = idx >> 5, c = idx & 31;
            ws[r][c] = W[(size_t)r * IN_DIM + k0 + c];
        }
        __syncthreads();
#pragma unroll
        for (int k = 0; k < 32; k++) {
            float av[4], bv[8];
#pragma unroll
            for (int v = 0; v < 4; v++) av[v] = hs[tm * 4 + v][k];
#pragma unroll
            for (int u = 0; u < 8; u++) bv[u] = ws[tn + 16 * u][k];
#pragma unroll
            for (int v = 0; v < 4; v++)
#pragma unroll
                for (int u = 0; u < 8; u++)
                    acc[v][u] += av[v] * bv[u];
        }
        __syncthreads();
    }
#pragma unroll
    for (int v = 0; v < 4; v++) {
        int i = m0 + tm * 4 + v;
#pragma unroll
        for (int u = 0; u < 8; u++) {
            int hd = tn + 16 * u;
            g_Whb[(size_t)i * H_DIM + hd] = __float2bfloat16(acc[v][u] + b[hd]);
        }
    }
}

// ---------------------------------------------------------------------------
// Kernel 3: per-row denom + bitmask (adj read once; NO exp in the loop)
// ---------------------------------------------------------------------------
__global__ __launch_bounds__(256) void k_denom(const float* __restrict__ adj) {
    const int i    = blockIdx.x;
    const int t    = threadIdx.x;
    const int lane = t & 31;
    const int wid  = t >> 5;

    const float nsi = -__ldg(&g_s[i]);
    const float Ei  = __ldg(&g_E[i]);
    const float E2i = __ldg(&g_E2[i]);
    const float4* __restrict__ row4 = (const float4*)(adj + (size_t)i * N_NODES);
    const float4* __restrict__ s4   = (const float4*)g_s;
    const float4* __restrict__ E4   = (const float4*)g_E;
    const float4* __restrict__ E24  = (const float4*)g_E2;
    uint4* __restrict__ mrow = (uint4*)(g_mask + (size_t)i * MASK_WPR);

    float dsum = 0.f;
#pragma unroll
    for (int step = 0; step < 8; step++) {
        int grp = wid * 8 + step;
        int c4  = grp * 32 + lane;
        float4 a4  = __ldcs(&row4[c4]);
        float4 sj  = __ldg(&s4[c4]);
        float4 Ej  = __ldg(&E4[c4]);
        float4 E2j = __ldg(&E24[c4]);
        unsigned nib = (a4.x != 0.f) | ((a4.y != 0.f) << 1)
                     | ((a4.z != 0.f) << 2) | ((a4.w != 0.f) << 3);
        unsigned b0 = __ballot_sync(0xffffffffu, nib & 1u);
        unsigned b1 = __ballot_sync(0xffffffffu, nib & 2u);
        unsigned b2 = __ballot_sync(0xffffffffu, nib & 4u);
        unsigned b3 = __ballot_sync(0xffffffffu, nib & 8u);
        if (lane == 0) mrow[grp] = make_uint4(b0, b1, b2, b3);

        float e0 = (sj.x > nsi) ? Ei * Ej.x : E2i * E2j.x;
        float e1 = (sj.y > nsi) ? Ei * Ej.y : E2i * E2j.y;
        float e2 = (sj.z > nsi) ? Ei * Ej.z : E2i * E2j.z;
        float e3 = (sj.w > nsi) ? Ei * Ej.w : E2i * E2j.w;
        if (a4.x != 0.f) dsum += e0;
        if (a4.y != 0.f) dsum += e1;
        if (a4.z != 0.f) dsum += e2;
        if (a4.w != 0.f) dsum += e3;
    }
#pragma unroll
    for (int o = 16; o; o >>= 1) dsum += __shfl_xor_sync(0xffffffffu, dsum, o);
    __shared__ float red[8];
    if (lane == 0) red[wid] = dsum;
    __syncthreads();
    if (t == 0) {
        float tot = 0.f;
#pragma unroll
        for (int w = 0; w < 8; w++) tot += red[w];
        g_inv[i] = (tot > 0.f) ? 1.f / tot : 0.f;
    }
}

// ---------------------------------------------------------------------------
// Kernel 4 (fused): RT=64, JSPLIT=2, grid 256, 2 CTAs/SM; NO exp in the loop.
// ---------------------------------------------------------------------------
#define RT 64
#define CT 128
#define NTH 256
#define JSPLIT 2
#define CHUNKS (N_NODES / CT / JSPLIT)     // 32 per CTA
#define APAD 136
#define ROWB (APAD * 2)
#define AS_BYTES (RT * APAD * 2)           // 17408
#define BS_BYTES (CT * APAD * 2)           // 34816
#define OFF_BS   (2 * AS_BYTES)
#define OFF_SL   (OFF_BS + 2 * BS_BYTES)
#define SMEM_TOTAL (OFF_SL + 3 * RT * 4)   // 105,216 B

__device__ __forceinline__ void mma16816(float* c, const unsigned* a,
                                         unsigned b0, unsigned b1) {
    asm volatile(
        "mma.sync.aligned.m16n8k16.row.col.f32.bf16.bf16.f32 "
        "{%0,%1,%2,%3}, {%4,%5,%6,%7}, {%8,%9}, {%0,%1,%2,%3};"
        : "+f"(c[0]), "+f"(c[1]), "+f"(c[2]), "+f"(c[3])
        : "r"(a[0]), "r"(a[1]), "r"(a[2]), "r"(a[3]), "r"(b0), "r"(b1));
}

__device__ __forceinline__ void cp16(unsigned dst, const void* src) {
    asm volatile("cp.async.cg.shared.global [%0], [%1], 16;\n"
                 :: "r"(dst), "l"(src));
}

__device__ __forceinline__ void alpha_tile(
    __nv_bfloat16* Ad, float* __restrict__ alpha_out,
    const uint4* m4g, const float4* s4g, const float4* E4g, const float4* E24g,
    const float* sNS, const float* sEA, const float* sEB,
    int i0, int jc, int wid, int lane)
{
    float4 sj  = __ldg(&s4g [jc * 32 + lane]);
    float4 Ej  = __ldg(&E4g [jc * 32 + lane]);
    float4 E2j = __ldg(&E24g[jc * 32 + lane]);
#pragma unroll
    for (int p = 0; p < 8; p++) {
        int r = wid * 8 + p;
        uint4 mw = __ldg(&m4g[(size_t)(i0 + r) * (MASK_WPR / 4) + jc]);
        float nsi = sNS[r], eA = sEA[r], eB = sEB[r];
        float4 ex;
        ex.x = ((mw.x >> lane) & 1u)
             ? ((sj.x > nsi) ? eA * Ej.x : eB * E2j.x) : 0.f;
        ex.y = ((mw.y >> lane) & 1u)
             ? ((sj.y > nsi) ? eA * Ej.y : eB * E2j.y) : 0.f;
        ex.z = ((mw.z >> lane) & 1u)
             ? ((sj.z > nsi) ? eA * Ej.z : eB * E2j.z) : 0.f;
        ex.w = ((mw.w >> lane) & 1u)
             ? ((sj.w > nsi) ? eA * Ej.w : eB * E2j.w) : 0.f;
        __stcs((float4*)(alpha_out + (size_t)(i0 + r) * N_NODES
                         + (size_t)jc * CT) + lane, ex);
        __nv_bfloat162* dst = (__nv_bfloat162*)&Ad[r * APAD + lane * 4];
        dst[0] = __float22bfloat162_rn(make_float2(ex.x, ex.y));
        dst[1] = __float22bfloat162_rn(make_float2(ex.z, ex.w));
    }
}

__global__ __launch_bounds__(NTH, 2) void k_fused(float* __restrict__ alpha_out) {
    extern __shared__ char smem[];
    __nv_bfloat16* As  = (__nv_bfloat16*)smem;            // 2 buffers
    float*         sNS = (float*)(smem + OFF_SL);         // -s_i
    float*         sEA = sNS + RT;                        // E[i]*inv
    float*         sEB = sEA + RT;                        // E2[i]*inv

    const int t    = threadIdx.x;
    const int lane = t & 31;
    const int wid  = t >> 5;                 // 0..7
    const int ib   = blockIdx.x & 127;
    const int js   = blockIdx.x >> 7;
    const int i0   = ib * RT;
    const int c0   = js * CHUNKS;

    const unsigned as_base = (unsigned)__cvta_generic_to_shared(As);
    const unsigned bs_base = (unsigned)__cvta_generic_to_shared(smem + OFF_BS);

    if (t < RT) {
        float inv = g_inv[i0 + t];
        sNS[t] = -g_s[i0 + t];
        sEA[t] = g_E [i0 + t] * inv;
        sEB[t] = g_E2[i0 + t] * inv;
    }

    // prologue: Bs chunk c0
    {
        const char* src = (const char*)(g_Whb + (size_t)c0 * CT * H_DIM);
#pragma unroll
        for (int p = 0; p < 8; p++) {
            int idx = t + p * NTH;
            int jr = idx >> 4, u = idx & 15;
            cp16(bs_base + jr * ROWB + u * 16, src + idx * 16);
        }
        asm volatile("cp.async.commit_group;");
    }
    __syncthreads();   // tables ready

    const float4* s4g  = (const float4*)g_s;
    const float4* E4g  = (const float4*)g_E;
    const float4* E24g = (const float4*)g_E2;
    const uint4*  m4g  = (const uint4*)g_mask;

    // alpha chunk c0 -> As[0]
    alpha_tile(As, alpha_out, m4g, s4g, E4g, E24g, sNS, sEA, sEB,
               i0, c0, wid, lane);
    asm volatile("cp.async.wait_group 0;");
    __syncthreads();

    const int wm = wid >> 1;     // 0..3 -> rows wm*16
    const int wn = wid & 1;      // 0..1 -> cols wn*64
    float acc[8][4];
#pragma unroll
    for (int n = 0; n < 8; n++)
#pragma unroll
        for (int c = 0; c < 4; c++) acc[n][c] = 0.f;

    const unsigned a_off0 = (wm * 16 + (lane & 15)) * ROWB + ((lane >> 4) * 8) * 2;
    const unsigned b_rowsel = (lane & 15);
    const unsigned b_colsel = (lane >> 4) * 8;

    for (int cc = 0; cc < CHUNKS; cc++) {
        const int buf = cc & 1;
        const int jc  = c0 + cc;

        if (cc + 1 < CHUNKS) {
            const char* src = (const char*)(g_Whb + (size_t)(jc + 1) * CT * H_DIM);
            const unsigned bdst = bs_base + (buf ^ 1) * BS_BYTES;
#pragma unroll
            for (int p = 0; p < 8; p++) {
                int idx = t + p * NTH;
                int jr = idx >> 4, u = idx & 15;
                cp16(bdst + jr * ROWB + u * 16, src + idx * 16);
            }
            asm volatile("cp.async.commit_group;");
            alpha_tile(As + (buf ^ 1) * (RT * APAD), alpha_out,
                       m4g, s4g, E4g, E24g, sNS, sEA, sEB,
                       i0, jc + 1, wid, lane);
        }

        // MMA As[buf] x Bs[buf]
        const unsigned abuf = as_base + buf * AS_BYTES + a_off0;
        const unsigned bbuf = bs_base + buf * BS_BYTES;
#pragma unroll
        for (int kk = 0; kk < CT; kk += 16) {
            unsigned a[4];
            asm volatile(
                "ldmatrix.sync.aligned.m8n8.x4.shared.b16 {%0,%1,%2,%3}, [%4];"
                : "=r"(a[0]), "=r"(a[1]), "=r"(a[2]), "=r"(a[3])
                : "r"(abuf + kk * 2));
#pragma unroll
            for (int nt = 0; nt < 4; nt++) {
                int n0 = wn * 64 + nt * 16;
                unsigned baddr = bbuf + (kk + b_rowsel) * ROWB
                                      + (n0 + b_colsel) * 2;
                unsigned b[4];
                asm volatile(
                    "ldmatrix.sync.aligned.m8n8.x4.trans.shared.b16 "
                    "{%0,%1,%2,%3}, [%4];"
                    : "=r"(b[0]), "=r"(b[1]), "=r"(b[2]), "=r"(b[3])
                    : "r"(baddr));
                mma16816(acc[nt * 2 + 0], a, b[0], b[1]);
                mma16816(acc[nt * 2 + 1], a, b[2], b[3]);
            }
        }

        if (cc + 1 < CHUNKS)
            asm volatile("cp.async.wait_group 0;");
        __syncthreads();
    }

    // epilogue: write fp32 partials
    float* part = g_part + (size_t)js * N_NODES * H_DIM;
    const int g = lane >> 2, q = lane & 3;
    const size_t r0 = (size_t)(i0 + wm * 16 + g) * H_DIM;
    const size_t r1 = r0 + 8 * H_DIM;
#pragma unroll
    for (int m = 0; m < 8; m++) {
        int col = wn * 64 + m * 8 + 2 * q;
        part[r0 + col]     = acc[m][0];
        part[r0 + col + 1] = acc[m][1];
        part[r1 + col]     = acc[m][2];
        part[r1 + col + 1] = acc[m][3];
    }
}

// ---------------------------------------------------------------------------
// Kernel 5: z = sigmoid(part0 + part1)
// ---------------------------------------------------------------------------
__global__ __launch_bounds__(256) void k_z(float* __restrict__ z_out) {
    int idx = blockIdx.x * 256 + threadIdx.x;      // float4 index
    const float4* p0 = (const float4*)g_part;
    const float4* p1 = (const float4*)(g_part + (size_t)N_NODES * H_DIM);
    float4 u = p0[idx], v = p1[idx];
    float4 z;
    z.x = 1.f / (1.f + __expf(-(u.x + v.x)));
    z.y = 1.f / (1.f + __expf(-(u.y + v.y)));
    z.z = 1.f / (1.f + __expf(-(u.z + v.z)));
    z.w = 1.f / (1.f + __expf(-(u.w + v.w)));
    ((float4*)z_out)[idx] = z;
}

// ---------------------------------------------------------------------------
extern "C" void kernel_launch(void* const* d_in, const int* in_sizes, int n_in,
                              void* d_out, int out_size) {
    const float* h   = (const float*)d_in[0];  // (8192, 512)
    const float* adj = (const float*)d_in[1];  // (8192, 8192)
    const float* W   = (const float*)d_in[2];  // (128, 512)
    const float* b   = (const float*)d_in[3];  // (128,)
    const float* a   = (const float*)d_in[4];  // (1, 128)

    float* z_out     = (float*)d_out;
    float* alpha_out = z_out + (size_t)N_NODES * H_DIM;

    k_wa<<<IN_DIM / 256, 256>>>(W, a);
    k_s<<<N_NODES / 8, 256>>>(h);
    k_gemm_wh<<<N_NODES / 64, 256>>>(h, W, b);
    k_denom<<<N_NODES, 256>>>(adj);

    cudaFuncSetAttribute(k_fused, cudaFuncAttributeMaxDynamicSharedMemorySize,
                         SMEM_TOTAL);
    k_fused<<<128 * JSPLIT, NTH, SMEM_TOTAL>>>(alpha_out);

    k_z<<<(N_NODES * H_DIM / 4) / 256, 256>>>(z_out);
}

// round 9
// speedup vs baseline: 1.7241x; 1.1448x over previous
#include <cuda_runtime.h>
#include <cuda_bf16.h>
#include <math.h>

#define N_NODES 8192
#define IN_DIM  512
#define H_DIM   128
#define MASK_WPR (N_NODES / 32)   // 256 mask words per row

// Common MMA tile constants (shared by k_gemm_tc and k_fused)
#define RT 64
#define CT 128
#define NTH 256
#define APAD 136
#define ROWB (APAD * 2)
#define AS_BYTES (RT * APAD * 2)           // 17408
#define BS_BYTES (CT * APAD * 2)           // 34816

// Scratch (allocation-free: __device__ globals)
__device__ __nv_bfloat16 g_Whb [(size_t)N_NODES * H_DIM];    // 2 MB bf16
__device__ __nv_bfloat16 g_WbT [(size_t)IN_DIM * H_DIM];     // 128 KB bf16 (W^T, k-major)
__device__ float         g_E   [N_NODES];   // exp(s)
__device__ float         g_E2  [N_NODES];   // exp(0.2 s)
__device__ float         g_inv [N_NODES];
__device__ float         g_wa  [IN_DIM];
__device__ unsigned      g_mask[(size_t)N_NODES * MASK_WPR]; // 8 MB bitmask
__device__ float         g_part[2 * (size_t)N_NODES * H_DIM]; // 8 MB partials

__device__ __forceinline__ void mma16816(float* c, const unsigned* a,
                                         unsigned b0, unsigned b1) {
    asm volatile(
        "mma.sync.aligned.m16n8k16.row.col.f32.bf16.bf16.f32 "
        "{%0,%1,%2,%3}, {%4,%5,%6,%7}, {%8,%9}, {%0,%1,%2,%3};"
        : "+f"(c[0]), "+f"(c[1]), "+f"(c[2]), "+f"(c[3])
        : "r"(a[0]), "r"(a[1]), "r"(a[2]), "r"(a[3]), "r"(b0), "r"(b1));
}

__device__ __forceinline__ void cp16(unsigned dst, const void* src) {
    asm volatile("cp.async.cg.shared.global [%0], [%1], 16;\n"
                 :: "r"(dst), "l"(src));
}

// ---------------------------------------------------------------------------
// Kernel 0a: wa = W^T @ a
// ---------------------------------------------------------------------------
__global__ __launch_bounds__(256) void k_wa(const float* __restrict__ W,
                                            const float* __restrict__ a) {
    int k = blockIdx.x * 256 + threadIdx.x;
    float sum = 0.f;
#pragma unroll 4
    for (int hd = 0; hd < H_DIM; hd++)
        sum += a[hd] * W[(size_t)hd * IN_DIM + k];
    g_wa[k] = sum;
}

// ---------------------------------------------------------------------------
// Kernel 0b: WbT[k][n] = bf16(W[n][k])   (512x128)
// ---------------------------------------------------------------------------
__global__ __launch_bounds__(256) void k_wt(const float* __restrict__ W) {
    int idx = blockIdx.x * 256 + threadIdx.x;   // 0..65535
    int k = idx >> 7, n = idx & 127;
    g_WbT[idx] = __float2bfloat16(W[(size_t)n * IN_DIM + k]);
}

// ---------------------------------------------------------------------------
// Kernel 1: s = h.wa (fp32 exact); store E = exp(s), E2 = exp(0.2 s)
// ---------------------------------------------------------------------------
__global__ __launch_bounds__(256) void k_s(const float* __restrict__ h) {
    int row  = (blockIdx.x * blockDim.x + threadIdx.x) >> 5;
    int lane = threadIdx.x & 31;
    const float4* h4  = (const float4*)(h + (size_t)row * IN_DIM);
    const float4* wa4 = (const float4*)g_wa;
    float d = 0.f;
#pragma unroll
    for (int u = 0; u < 4; u++) {
        float4 x = h4[lane + 32 * u];
        float4 y = __ldg(&wa4[lane + 32 * u]);
        d += x.x * y.x + x.y * y.y + x.z * y.z + x.w * y.w;
    }
#pragma unroll
    for (int o = 16; o; o >>= 1) d += __shfl_xor_sync(0xffffffffu, d, o);
    if (lane == 0) {
        g_E [row] = __expf(d);
        g_E2[row] = __expf(0.2f * d);
    }
}

// ---------------------------------------------------------------------------
// Kernel 2: Whb = bf16(h @ W^T + b) via bf16 tensor-core MMA.
// BM=64, BN=128, BK=128 (4 k-chunks). Reuses the fused kernel's proven
// ldmatrix/MMA/epilogue mapping exactly (B path identical to Whb path).
// ---------------------------------------------------------------------------
#define GT_SMEM (2 * AS_BYTES + 2 * BS_BYTES + H_DIM * 4)

__global__ __launch_bounds__(NTH, 2) void k_gemm_tc(const float* __restrict__ h,
                                                    const float* __restrict__ b) {
    extern __shared__ char smem[];
    __nv_bfloat16* As = (__nv_bfloat16*)smem;                     // 2 buffers
    float* sbias = (float*)(smem + 2 * AS_BYTES + 2 * BS_BYTES);

    const int t    = threadIdx.x;
    const int lane = t & 31;
    const int wid  = t >> 5;
    const int m0   = blockIdx.x * RT;

    const unsigned as_base = (unsigned)__cvta_generic_to_shared(As);
    const unsigned bs_base = (unsigned)__cvta_generic_to_shared(smem + 2 * AS_BYTES);

    if (t < H_DIM) sbias[t] = b[t];

    // prologue: LDG A chunk 0 + cp.async B chunk 0
    float4 av[8];
#pragma unroll
    for (int p = 0; p < 8; p++) {
        int idx = t + p * NTH;
        int r = idx >> 5, c4 = idx & 31;
        av[p] = __ldg((const float4*)(h + (size_t)(m0 + r) * IN_DIM) + c4);
    }
#pragma unroll
    for (int p = 0; p < 8; p++) {
        int idx = t + p * NTH;
        int jr = idx >> 4, u = idx & 15;
        cp16(bs_base + jr * ROWB + u * 16, (const char*)g_WbT + idx * 16);
    }
    asm volatile("cp.async.commit_group;");
    // convert + store A chunk 0
#pragma unroll
    for (int p = 0; p < 8; p++) {
        int idx = t + p * NTH;
        int r = idx >> 5, c4 = idx & 31;
        __nv_bfloat162* dst = (__nv_bfloat162*)&As[r * APAD + c4 * 4];
        dst[0] = __float22bfloat162_rn(make_float2(av[p].x, av[p].y));
        dst[1] = __float22bfloat162_rn(make_float2(av[p].z, av[p].w));
    }
    asm volatile("cp.async.wait_group 0;");
    __syncthreads();

    const int wm = wid >> 1;     // 0..3
    const int wn = wid & 1;      // 0..1
    float acc[8][4];
#pragma unroll
    for (int n = 0; n < 8; n++)
#pragma unroll
        for (int c = 0; c < 4; c++) acc[n][c] = 0.f;

    const unsigned a_off0 = (wm * 16 + (lane & 15)) * ROWB + ((lane >> 4) * 8) * 2;
    const unsigned b_rowsel = (lane & 15);
    const unsigned b_colsel = (lane >> 4) * 8;

#pragma unroll
    for (int c = 0; c < IN_DIM / CT; c++) {     // 4 chunks
        const int buf = c & 1;

        if (c + 1 < IN_DIM / CT) {
#pragma unroll
            for (int p = 0; p < 8; p++) {
                int idx = t + p * NTH;
                int r = idx >> 5, c4 = idx & 31;
                av[p] = __ldg((const float4*)(h + (size_t)(m0 + r) * IN_DIM
                                              + (c + 1) * CT) + c4);
            }
            const char* src = (const char*)(g_WbT + (size_t)(c + 1) * CT * H_DIM);
            const unsigned bdst = bs_base + (buf ^ 1) * BS_BYTES;
#pragma unroll
            for (int p = 0; p < 8; p++) {
                int idx = t + p * NTH;
                int jr = idx >> 4, u = idx & 15;
                cp16(bdst + jr * ROWB + u * 16, src + idx * 16);
            }
            asm volatile("cp.async.commit_group;");
        }

        // MMA As[buf] x Bs[buf]  (identical mapping to k_fused)
        const unsigned abuf = as_base + buf * AS_BYTES + a_off0;
        const unsigned bbuf = bs_base + buf * BS_BYTES;
#pragma unroll
        for (int kk = 0; kk < CT; kk += 16) {
            unsigned a[4];
            asm volatile(
                "ldmatrix.sync.aligned.m8n8.x4.shared.b16 {%0,%1,%2,%3}, [%4];"
                : "=r"(a[0]), "=r"(a[1]), "=r"(a[2]), "=r"(a[3])
                : "r"(abuf + kk * 2));
#pragma unroll
            for (int nt = 0; nt < 4; nt++) {
                int n0 = wn * 64 + nt * 16;
                unsigned baddr = bbuf + (kk + b_rowsel) * ROWB
                                      + (n0 + b_colsel) * 2;
                unsigned bb[4];
                asm volatile(
                    "ldmatrix.sync.aligned.m8n8.x4.trans.shared.b16 "
                    "{%0,%1,%2,%3}, [%4];"
                    : "=r"(bb[0]), "=r"(bb[1]), "=r"(bb[2]), "=r"(bb[3])
                    : "r"(baddr));
                mma16816(acc[nt * 2 + 0], a, bb[0], bb[1]);
                mma16816(acc[nt * 2 + 1], a, bb[2], bb[3]);
            }
        }

        if (c + 1 < IN_DIM / CT) {
            __nv_bfloat16* Ad = As + (buf ^ 1) * (RT * APAD);
#pragma unroll
            for (int p = 0; p < 8; p++) {
                int idx = t + p * NTH;
                int r = idx >> 5, c4 = idx & 31;
                __nv_bfloat162* dst = (__nv_bfloat162*)&Ad[r * APAD + c4 * 4];
                dst[0] = __float22bfloat162_rn(make_float2(av[p].x, av[p].y));
                dst[1] = __float22bfloat162_rn(make_float2(av[p].z, av[p].w));
            }
            asm volatile("cp.async.wait_group 0;");
        }
        __syncthreads();
    }

    // epilogue: + bias, bf16 store
    const int g = lane >> 2, q = lane & 3;
    const int r0 = m0 + wm * 16 + g;
    const int r1 = r0 + 8;
#pragma unroll
    for (int m = 0; m < 8; m++) {
        int col = wn * 64 + m * 8 + 2 * q;
        g_Whb[(size_t)r0 * H_DIM + col]     = __float2bfloat16(acc[m][0] + sbias[col]);
        g_Whb[(size_t)r0 * H_DIM + col + 1] = __float2bfloat16(acc[m][1] + sbias[col + 1]);
        g_Whb[(size_t)r1 * H_DIM + col]     = __float2bfloat16(acc[m][2] + sbias[col]);
        g_Whb[(size_t)r1 * H_DIM + col + 1] = __float2bfloat16(acc[m][3] + sbias[col + 1]);
    }
}

// ---------------------------------------------------------------------------
// Kernel 3: per-row denom + bitmask. exp(lrelu(si+sj)) = max(EiEj, E2iE2j).
// Branch-free accumulate: dsum = fma(adj, e, dsum).
// ---------------------------------------------------------------------------
__global__ __launch_bounds__(256) void k_denom(const float* __restrict__ adj) {
    const int i    = blockIdx.x;
    const int t    = threadIdx.x;
    const int lane = t & 31;
    const int wid  = t >> 5;

    const float Ei  = __ldg(&g_E[i]);
    const float E2i = __ldg(&g_E2[i]);
    const float4* __restrict__ row4 = (const float4*)(adj + (size_t)i * N_NODES);
    const float4* __restrict__ E4   = (const float4*)g_E;
    const float4* __restrict__ E24  = (const float4*)g_E2;
    uint4* __restrict__ mrow = (uint4*)(g_mask + (size_t)i * MASK_WPR);

    float dsum = 0.f;
#pragma unroll
    for (int step = 0; step < 8; step++) {
        int grp = wid * 8 + step;
        int c4  = grp * 32 + lane;
        float4 a4  = __ldcs(&row4[c4]);
        float4 Ej  = __ldg(&E4[c4]);
        float4 E2j = __ldg(&E24[c4]);
        unsigned nib = (a4.x != 0.f) | ((a4.y != 0.f) << 1)
                     | ((a4.z != 0.f) << 2) | ((a4.w != 0.f) << 3);
        unsigned b0 = __ballot_sync(0xffffffffu, nib & 1u);
        unsigned b1 = __ballot_sync(0xffffffffu, nib & 2u);
        unsigned b2 = __ballot_sync(0xffffffffu, nib & 4u);
        unsigned b3 = __ballot_sync(0xffffffffu, nib & 8u);
        if (lane == 0) mrow[grp] = make_uint4(b0, b1, b2, b3);

        dsum = fmaf(a4.x, fmaxf(Ei * Ej.x, E2i * E2j.x), dsum);
        dsum = fmaf(a4.y, fmaxf(Ei * Ej.y, E2i * E2j.y), dsum);
        dsum = fmaf(a4.z, fmaxf(Ei * Ej.z, E2i * E2j.z), dsum);
        dsum = fmaf(a4.w, fmaxf(Ei * Ej.w, E2i * E2j.w), dsum);
    }
#pragma unroll
    for (int o = 16; o; o >>= 1) dsum += __shfl_xor_sync(0xffffffffu, dsum, o);
    __shared__ float red[8];
    if (lane == 0) red[wid] = dsum;
    __syncthreads();
    if (t == 0) {
        float tot = 0.f;
#pragma unroll
        for (int w = 0; w < 8; w++) tot += red[w];
        g_inv[i] = (tot > 0.f) ? 1.f / tot : 0.f;
    }
}

// ---------------------------------------------------------------------------
// Kernel 4 (fused): RT=64, JSPLIT=2, grid 256, 2 CTAs/SM, max-trick alpha.
// ---------------------------------------------------------------------------
#define JSPLIT 2
#define CHUNKS (N_NODES / CT / JSPLIT)     // 32 per CTA
#define OFF_BS   (2 * AS_BYTES)
#define OFF_SL   (OFF_BS + 2 * BS_BYTES)
#define SMEM_TOTAL (OFF_SL + 2 * RT * 4)

__device__ __forceinline__ void alpha_tile(
    __nv_bfloat16* Ad, float* __restrict__ alpha_out,
    const uint4* m4g, const float4* E4g, const float4* E24g,
    const float* sEA, const float* sEB,
    int i0, int jc, int wid, int lane)
{
    float4 Ej  = __ldg(&E4g [jc * 32 + lane]);
    float4 E2j = __ldg(&E24g[jc * 32 + lane]);
#pragma unroll
    for (int p = 0; p < 8; p++) {
        int r = wid * 8 + p;
        uint4 mw = __ldg(&m4g[(size_t)(i0 + r) * (MASK_WPR / 4) + jc]);
        float eA = sEA[r], eB = sEB[r];
        float4 ex;
        ex.x = ((mw.x >> lane) & 1u) ? fmaxf(eA * Ej.x, eB * E2j.x) : 0.f;
        ex.y = ((mw.y >> lane) & 1u) ? fmaxf(eA * Ej.y, eB * E2j.y) : 0.f;
        ex.z = ((mw.z >> lane) & 1u) ? fmaxf(eA * Ej.z, eB * E2j.z) : 0.f;
        ex.w = ((mw.w >> lane) & 1u) ? fmaxf(eA * Ej.w, eB * E2j.w) : 0.f;
        __stcs((float4*)(alpha_out + (size_t)(i0 + r) * N_NODES
                         + (size_t)jc * CT) + lane, ex);
        __nv_bfloat162* dst = (__nv_bfloat162*)&Ad[r * APAD + lane * 4];
        dst[0] = __float22bfloat162_rn(make_float2(ex.x, ex.y));
        dst[1] = __float22bfloat162_rn(make_float2(ex.z, ex.w));
    }
}

__global__ __launch_bounds__(NTH, 2) void k_fused(float* __restrict__ alpha_out) {
    extern __shared__ char smem[];
    __nv_bfloat16* As  = (__nv_bfloat16*)smem;            // 2 buffers
    float*         sEA = (float*)(smem + OFF_SL);         // E[i]*inv
    float*         sEB = sEA + RT;                        // E2[i]*inv

    const int t    = threadIdx.x;
    const int lane = t & 31;
    const int wid  = t >> 5;                 // 0..7
    const int ib   = blockIdx.x & 127;
    const int js   = blockIdx.x >> 7;
    const int i0   = ib * RT;
    const int c0   = js * CHUNKS;

    const unsigned as_base = (unsigned)__cvta_generic_to_shared(As);
    const unsigned bs_base = (unsigned)__cvta_generic_to_shared(smem + OFF_BS);

    if (t < RT) {
        float inv = g_inv[i0 + t];
        sEA[t] = g_E [i0 + t] * inv;
        sEB[t] = g_E2[i0 + t] * inv;
    }

    // prologue: Bs chunk c0
    {
        const char* src = (const char*)(g_Whb + (size_t)c0 * CT * H_DIM);
#pragma unroll
        for (int p = 0; p < 8; p++) {
            int idx = t + p * NTH;
            int jr = idx >> 4, u = idx & 15;
            cp16(bs_base + jr * ROWB + u * 16, src + idx * 16);
        }
        asm volatile("cp.async.commit_group;");
    }
    __syncthreads();

    const float4* E4g  = (const float4*)g_E;
    const float4* E24g = (const float4*)g_E2;
    const uint4*  m4g  = (const uint4*)g_mask;

    alpha_tile(As, alpha_out, m4g, E4g, E24g, sEA, sEB, i0, c0, wid, lane);
    asm volatile("cp.async.wait_group 0;");
    __syncthreads();

    const int wm = wid >> 1;
    const int wn = wid & 1;
    float acc[8][4];
#pragma unroll
    for (int n = 0; n < 8; n++)
#pragma unroll
        for (int c = 0; c < 4; c++) acc[n][c] = 0.f;

    const unsigned a_off0 = (wm * 16 + (lane & 15)) * ROWB + ((lane >> 4) * 8) * 2;
    const unsigned b_rowsel = (lane & 15);
    const unsigned b_colsel = (lane >> 4) * 8;

    for (int cc = 0; cc < CHUNKS; cc++) {
        const int buf = cc & 1;
        const int jc  = c0 + cc;

        if (cc + 1 < CHUNKS) {
            const char* src = (const char*)(g_Whb + (size_t)(jc + 1) * CT * H_DIM);
            const unsigned bdst = bs_base + (buf ^ 1) * BS_BYTES;
#pragma unroll
            for (int p = 0; p < 8; p++) {
                int idx = t + p * NTH;
                int jr = idx >> 4, u = idx & 15;
                cp16(bdst + jr * ROWB + u * 16, src + idx * 16);
            }
            asm volatile("cp.async.commit_group;");
            alpha_tile(As + (buf ^ 1) * (RT * APAD), alpha_out,
                       m4g, E4g, E24g, sEA, sEB, i0, jc + 1, wid, lane);
        }

        const unsigned abuf = as_base + buf * AS_BYTES + a_off0;
        const unsigned bbuf = bs_base + buf * BS_BYTES;
#pragma unroll
        for (int kk = 0; kk < CT; kk += 16) {
            unsigned a[4];
            asm volatile(
                "ldmatrix.sync.aligned.m8n8.x4.shared.b16 {%0,%1,%2,%3}, [%4];"
                : "=r"(a[0]), "=r"(a[1]), "=r"(a[2]), "=r"(a[3])
                : "r"(abuf + kk * 2));
#pragma unroll
            for (int nt = 0; nt < 4; nt++) {
                int n0 = wn * 64 + nt * 16;
                unsigned baddr = bbuf + (kk + b_rowsel) * ROWB
                                      + (n0 + b_colsel) * 2;
                unsigned bb[4];
                asm volatile(
                    "ldmatrix.sync.aligned.m8n8.x4.trans.shared.b16 "
                    "{%0,%1,%2,%3}, [%4];"
                    : "=r"(bb[0]), "=r"(bb[1]), "=r"(bb[2]), "=r"(bb[3])
                    : "r"(baddr));
                mma16816(acc[nt * 2 + 0], a, bb[0], bb[1]);
                mma16816(acc[nt * 2 + 1], a, bb[2], bb[3]);
            }
        }

        if (cc + 1 < CHUNKS)
            asm volatile("cp.async.wait_group 0;");
        __syncthreads();
    }

    // epilogue: write fp32 partials
    float* part = g_part + (size_t)js * N_NODES * H_DIM;
    const int g = lane >> 2, q = lane & 3;
    const size_t r0 = (size_t)(i0 + wm * 16 + g) * H_DIM;
    const size_t r1 = r0 + 8 * H_DIM;
#pragma unroll
    for (int m = 0; m < 8; m++) {
        int col = wn * 64 + m * 8 + 2 * q;
        part[r0 + col]     = acc[m][0];
        part[r0 + col + 1] = acc[m][1];
        part[r1 + col]     = acc[m][2];
        part[r1 + col + 1] = acc[m][3];
    }
}

// ---------------------------------------------------------------------------
// Kernel 5: z = sigmoid(part0 + part1)
// ---------------------------------------------------------------------------
__global__ __launch_bounds__(256) void k_z(float* __restrict__ z_out) {
    int idx = blockIdx.x * 256 + threadIdx.x;
    const float4* p0 = (const float4*)g_part;
    const float4* p1 = (const float4*)(g_part + (size_t)N_NODES * H_DIM);
    float4 u = p0[idx], v = p1[idx];
    float4 z;
    z.x = 1.f / (1.f + __expf(-(u.x + v.x)));
    z.y = 1.f / (1.f + __expf(-(u.y + v.y)));
    z.z = 1.f / (1.f + __expf(-(u.z + v.z)));
    z.w = 1.f / (1.f + __expf(-(u.w + v.w)));
    ((float4*)z_out)[idx] = z;
}

// ---------------------------------------------------------------------------
extern "C" void kernel_launch(void* const* d_in, const int* in_sizes, int n_in,
                              void* d_out, int out_size) {
    const float* h   = (const float*)d_in[0];  // (8192, 512)
    const float* adj = (const float*)d_in[1];  // (8192, 8192)
    const float* W   = (const float*)d_in[2];  // (128, 512)
    const float* b   = (const float*)d_in[3];  // (128,)
    const float* a   = (const float*)d_in[4];  // (1, 128)

    float* z_out     = (float*)d_out;
    float* alpha_out = z_out + (size_t)N_NODES * H_DIM;

    k_wa<<<IN_DIM / 256, 256>>>(W, a);
    k_s<<<N_NODES / 8, 256>>>(h);
    k_wt<<<IN_DIM * H_DIM / 256, 256>>>(W);

    cudaFuncSetAttribute(k_gemm_tc, cudaFuncAttributeMaxDynamicSharedMemorySize,
                         GT_SMEM);
    k_gemm_tc<<<N_NODES / RT, NTH, GT_SMEM>>>(h, b);

    k_denom<<<N_NODES, 256>>>(adj);

    cudaFuncSetAttribute(k_fused, cudaFuncAttributeMaxDynamicSharedMemorySize,
                         SMEM_TOTAL);
    k_fused<<<128 * JSPLIT, NTH, SMEM_TOTAL>>>(alpha_out);

    k_z<<<(N_NODES * H_DIM / 4) / 256, 256>>>(z_out);
}